// round 2
// baseline (speedup 1.0000x reference)
#include <cuda_runtime.h>

// Problem: LIF spiking layer.
//   x: (T=256, B=128, I=512) f32   -> d_in[0]
//   W: (H=512, I=512) f32          -> d_in[1]
//   b: (H=512,) f32                -> d_in[2]
//   h = x @ W^T + b  (GEMM M=32768, N=512, K=512)
//   scan over T per neuron: v = 0.5*v + h_t; s = (v>=1); v = s ? 0 : v
//   out: spikes (T,B,H) f32

#define M_TOT 32768
#define N_TOT 512
#define K_TOT 512
#define T_STEPS 256
#define BH 65536   // B*H = per-timestep plane size

#define BM 128
#define BN 128
#define BK 16

// Scratch for h = x@W^T + b  (M_TOT * N_TOT floats = 64 MB). Device global:
// allocation-free per harness rules.
__device__ float g_h[M_TOT * N_TOT];

// ---------------------------------------------------------------------------
// Phase 1: fp32 SIMT GEMM, C = A @ B^T + bias.
// A = x (M x K row-major, K contiguous), B = W (N x K row-major, K contiguous).
// 128x128 CTA tile, 256 threads, 8x8 per-thread tile, BK=16.
// Full fp32 accumulation (precision matters: output spikes are chaotic in h).
// ---------------------------------------------------------------------------
__global__ __launch_bounds__(256, 2)
void gemm_bias_kernel(const float* __restrict__ A,
                      const float* __restrict__ Bw,
                      const float* __restrict__ bias) {
    __shared__ float As[BK][BM + 4];   // stored transposed: As[k][m]
    __shared__ float Bs[BK][BN + 4];   // Bs[k][n]

    const int bn = blockIdx.x * BN;
    const int bm = blockIdx.y * BM;
    const int tid = (int)threadIdx.x;
    const int tx = tid & 15;          // n sub-tile
    const int ty = tid >> 4;          // m sub-tile
    const int lrow = tid >> 2;        // 0..63, load row
    const int lk = (tid & 3) << 2;    // 0,4,8,12 load k-offset

    const float* Aptr = A + (long)bm * K_TOT;
    const float* Bptr = Bw + (long)bn * K_TOT;

    float acc[8][8];
#pragma unroll
    for (int i = 0; i < 8; i++)
#pragma unroll
        for (int j = 0; j < 8; j++) acc[i][j] = 0.0f;

    for (int k0 = 0; k0 < K_TOT; k0 += BK) {
        // Load 128x16 tiles of A and W into smem (transposed to [k][row]).
#pragma unroll
        for (int r = 0; r < 2; r++) {
            const int row = lrow + r * 64;
            float4 va = *reinterpret_cast<const float4*>(Aptr + (long)row * K_TOT + k0 + lk);
            As[lk + 0][row] = va.x;
            As[lk + 1][row] = va.y;
            As[lk + 2][row] = va.z;
            As[lk + 3][row] = va.w;
            float4 vb = *reinterpret_cast<const float4*>(Bptr + (long)row * K_TOT + k0 + lk);
            Bs[lk + 0][row] = vb.x;
            Bs[lk + 1][row] = vb.y;
            Bs[lk + 2][row] = vb.z;
            Bs[lk + 3][row] = vb.w;
        }
        __syncthreads();

#pragma unroll
        for (int kk = 0; kk < BK; kk++) {
            float a[8], b[8];
            float4 a0 = *reinterpret_cast<const float4*>(&As[kk][ty * 8]);
            float4 a1 = *reinterpret_cast<const float4*>(&As[kk][ty * 8 + 4]);
            float4 b0 = *reinterpret_cast<const float4*>(&Bs[kk][tx * 8]);
            float4 b1 = *reinterpret_cast<const float4*>(&Bs[kk][tx * 8 + 4]);
            a[0] = a0.x; a[1] = a0.y; a[2] = a0.z; a[3] = a0.w;
            a[4] = a1.x; a[5] = a1.y; a[6] = a1.z; a[7] = a1.w;
            b[0] = b0.x; b[1] = b0.y; b[2] = b0.z; b[3] = b0.w;
            b[4] = b1.x; b[5] = b1.y; b[6] = b1.z; b[7] = b1.w;
#pragma unroll
            for (int i = 0; i < 8; i++)
#pragma unroll
                for (int j = 0; j < 8; j++)
                    acc[i][j] = fmaf(a[i], b[j], acc[i][j]);
        }
        __syncthreads();
    }

    // Epilogue: add bias, store to g_h.
#pragma unroll
    for (int i = 0; i < 8; i++) {
        const int row = bm + ty * 8 + i;
#pragma unroll
        for (int j = 0; j < 8; j += 4) {
            const int col = bn + tx * 8 + j;
            float4 o;
            o.x = acc[i][j + 0] + bias[col + 0];
            o.y = acc[i][j + 1] + bias[col + 1];
            o.z = acc[i][j + 2] + bias[col + 2];
            o.w = acc[i][j + 3] + bias[col + 3];
            *reinterpret_cast<float4*>(&g_h[(long)row * N_TOT + col]) = o;
        }
    }
}

// ---------------------------------------------------------------------------
// Phase 2: LIF scan. One thread per neuron (b,h); sequential over T.
// Exactly reproduces reference fp behavior:
//   v - (v-0)/2 + h  == fma(0.5f, v, h)  (halving is exact in fp32)
//   spike(v - 1)     == (v >= 1.0f)
//   v*(1-s)          == s ? 0 : v
// Unroll by 4 for load MLP (independent addresses).
// ---------------------------------------------------------------------------
__global__ __launch_bounds__(256)
void lif_scan_kernel(float* __restrict__ out) {
    const int idx = blockIdx.x * blockDim.x + threadIdx.x;  // 0..65535
    const float* hp = g_h + idx;
    float* op = out + idx;
    float v = 0.0f;

#pragma unroll 1
    for (int t = 0; t < T_STEPS; t += 4) {
        // 4 independent loads first (MLP)
        float h0 = hp[0 * BH];
        float h1 = hp[1 * BH];
        float h2 = hp[2 * BH];
        float h3 = hp[3 * BH];

        float s0, s1, s2, s3;
        v = fmaf(0.5f, v, h0); s0 = (v >= 1.0f) ? 1.0f : 0.0f; v = (v >= 1.0f) ? 0.0f : v;
        v = fmaf(0.5f, v, h1); s1 = (v >= 1.0f) ? 1.0f : 0.0f; v = (v >= 1.0f) ? 0.0f : v;
        v = fmaf(0.5f, v, h2); s2 = (v >= 1.0f) ? 1.0f : 0.0f; v = (v >= 1.0f) ? 0.0f : v;
        v = fmaf(0.5f, v, h3); s3 = (v >= 1.0f) ? 1.0f : 0.0f; v = (v >= 1.0f) ? 0.0f : v;

        op[0 * BH] = s0;
        op[1 * BH] = s1;
        op[2 * BH] = s2;
        op[3 * BH] = s3;

        hp += 4 * BH;
        op += 4 * BH;
    }
}

extern "C" void kernel_launch(void* const* d_in, const int* in_sizes, int n_in,
                              void* d_out, int out_size) {
    const float* x = (const float*)d_in[0];     // (256,128,512)
    const float* W = (const float*)d_in[1];     // (512,512)
    const float* b = (const float*)d_in[2];     // (512,)
    float* out = (float*)d_out;                 // (256,128,512)

    dim3 ggrid(N_TOT / BN, M_TOT / BM);         // (4, 256)
    gemm_bias_kernel<<<ggrid, 256>>>(x, W, b);

    lif_scan_kernel<<<BH / 256, 256>>>(out);
}

// round 4
// speedup vs baseline: 1.3475x; 1.3475x over previous
#include <cuda_runtime.h>
#include <cstdint>

// LIF spiking layer: h = x @ W^T + b  (M=32768, N=512, K=512), then
// sequential LIF scan over T=256: v = 0.5v + h_t; s = (v>=1); hard reset.
//
// sm_103 base target (no tcgen05 in this build!). GEMM = SIMT fp32 using
// packed fma.rn.f32x2 (FFMA2) to halve instruction count / use the f32x2
// pipe. Numerically identical to scalar fmaf chains (two independent rn
// FMAs per instruction) -> same rel_err=0.0 behavior as round 1.

#define M_TOT 32768
#define N_TOT 512
#define K_TOT 512
#define T_STEPS 256
#define BH 65536

#define BM 128
#define BN 128
#define BK 16
#define NCHUNK (K_TOT / BK)   // 32

__device__ float g_h[M_TOT * N_TOT];   // 64 MB scratch for h

typedef unsigned long long ull;

__device__ __forceinline__ void ffma2(ull& d, ull a, ull b) {
    // d.lo += a.lo*b.lo ; d.hi += a.hi*b.hi   (both rn, independent fp32 FMAs)
    asm("fma.rn.f32x2 %0, %1, %2, %0;" : "+l"(d) : "l"(a), "l"(b));
}

// ---------------------------------------------------------------------------
// GEMM: C = A @ B^T + bias -> g_h
// A = x (32768 x 512, K contiguous), B = W (512 x 512, K contiguous).
// 256 threads, 128x128 CTA tile, 8x8 per-thread tile.
// As stored DUPLICATED ([k][2m]=[k][2m+1]=a) so the broadcast operand of
// FFMA2 is one LDS.64. Bs stored transposed [k][n]; natural (b_{2j},b_{2j+1})
// pairs via LDS.64. Inner loop: 12 LDS.64 + 32 FFMA2 per k-step.
// ---------------------------------------------------------------------------
#define ASTRIDE (2 * BM + 8)   // 264 floats per k-row (dup'd), 8B-aligned pairs
#define BSTRIDE (BN + 4)       // 132

__global__ __launch_bounds__(256, 2)
void gemm_bias_kernel(const float* __restrict__ A,
                      const float* __restrict__ Bw,
                      const float* __restrict__ bias) {
    __shared__ float As[BK][ASTRIDE];
    __shared__ float Bs[BK][BSTRIDE];

    const int tid = (int)threadIdx.x;
    const int tx = tid & 15;           // n sub-tile (cols tx*8 .. tx*8+7)
    const int ty = tid >> 4;           // m sub-tile (rows ty*8 .. ty*8+7)
    const int lrow = tid >> 2;         // 0..63 loader row
    const int lk = (tid & 3) << 2;     // k offset 0,4,8,12
    const int bn = blockIdx.x * BN;
    const int bm = blockIdx.y * BM;

    const float* Aptr = A + (size_t)(bm)*K_TOT;
    const float* Bptr = Bw + (size_t)(bn)*K_TOT;

    ull acc[8][4];
#pragma unroll
    for (int i = 0; i < 8; i++)
#pragma unroll
        for (int j = 0; j < 4; j++) acc[i][j] = 0ull;

    // Prologue: stage chunk 0 in registers
    float4 ra0, ra1, rb0, rb1;
    {
        ra0 = *reinterpret_cast<const float4*>(Aptr + (size_t)lrow * K_TOT + lk);
        ra1 = *reinterpret_cast<const float4*>(Aptr + (size_t)(lrow + 64) * K_TOT + lk);
        rb0 = *reinterpret_cast<const float4*>(Bptr + (size_t)lrow * K_TOT + lk);
        rb1 = *reinterpret_cast<const float4*>(Bptr + (size_t)(lrow + 64) * K_TOT + lk);
    }

    for (int c = 0; c < NCHUNK; c++) {
        // Store staged regs to smem (A duplicated, B transposed)
        {
            const float av0[4] = {ra0.x, ra0.y, ra0.z, ra0.w};
            const float av1[4] = {ra1.x, ra1.y, ra1.z, ra1.w};
            const float bv0[4] = {rb0.x, rb0.y, rb0.z, rb0.w};
            const float bv1[4] = {rb1.x, rb1.y, rb1.z, rb1.w};
#pragma unroll
            for (int q = 0; q < 4; q++) {
                *reinterpret_cast<float2*>(&As[lk + q][2 * lrow]) =
                    make_float2(av0[q], av0[q]);
                *reinterpret_cast<float2*>(&As[lk + q][2 * (lrow + 64)]) =
                    make_float2(av1[q], av1[q]);
                Bs[lk + q][lrow] = bv0[q];
                Bs[lk + q][lrow + 64] = bv1[q];
            }
        }
        __syncthreads();

        // Stage next chunk (hidden under the compute below)
        if (c + 1 < NCHUNK) {
            const int ko = (c + 1) * BK + lk;
            ra0 = *reinterpret_cast<const float4*>(Aptr + (size_t)lrow * K_TOT + ko);
            ra1 = *reinterpret_cast<const float4*>(Aptr + (size_t)(lrow + 64) * K_TOT + ko);
            rb0 = *reinterpret_cast<const float4*>(Bptr + (size_t)lrow * K_TOT + ko);
            rb1 = *reinterpret_cast<const float4*>(Bptr + (size_t)(lrow + 64) * K_TOT + ko);
        }

        // Compute 16 k-steps
#pragma unroll
        for (int kk = 0; kk < BK; kk++) {
            const ull* bp = reinterpret_cast<const ull*>(&Bs[kk][tx * 8]);
            ull bv0 = bp[0], bv1 = bp[1], bv2 = bp[2], bv3 = bp[3];
            const ull* ap = reinterpret_cast<const ull*>(&As[kk][ty * 16]);
#pragma unroll
            for (int i = 0; i < 8; i++) {
                ull av = ap[i];
                ffma2(acc[i][0], av, bv0);
                ffma2(acc[i][1], av, bv1);
                ffma2(acc[i][2], av, bv2);
                ffma2(acc[i][3], av, bv3);
            }
        }
        __syncthreads();
    }

    // Epilogue: unpack, add bias, store
#pragma unroll
    for (int i = 0; i < 8; i++) {
        const int row = bm + ty * 8 + i;
        float* orow = g_h + (size_t)row * N_TOT + bn + tx * 8;
#pragma unroll
        for (int j = 0; j < 2; j++) {
            float4 o;
            o.x = __uint_as_float((unsigned)(acc[i][2 * j] & 0xffffffffu));
            o.y = __uint_as_float((unsigned)(acc[i][2 * j] >> 32));
            o.z = __uint_as_float((unsigned)(acc[i][2 * j + 1] & 0xffffffffu));
            o.w = __uint_as_float((unsigned)(acc[i][2 * j + 1] >> 32));
            const int cb = bn + tx * 8 + 4 * j;
            o.x += __ldg(bias + cb + 0);
            o.y += __ldg(bias + cb + 1);
            o.z += __ldg(bias + cb + 2);
            o.w += __ldg(bias + cb + 3);
            *reinterpret_cast<float4*>(orow + 4 * j) = o;
        }
    }
}

// ---------------------------------------------------------------------------
// LIF scan: 1 thread per neuron, sequential over T, unroll 16 for MLP.
//   v = fma(0.5,v,h) == v - v/2 + h exactly; spike at v>=1; reset v=0.
// ---------------------------------------------------------------------------
__global__ __launch_bounds__(256)
void lif_scan_kernel(float* __restrict__ out) {
    const int idx = blockIdx.x * 256 + threadIdx.x;   // 0..65535
    const float* hp = g_h + idx;
    float* op = out + idx;
    float v = 0.0f;

#pragma unroll 1
    for (int t = 0; t < T_STEPS; t += 16) {
        float h[16];
#pragma unroll
        for (int k = 0; k < 16; k++) h[k] = __ldcg(hp + (size_t)k * BH);
        float sp[16];
#pragma unroll
        for (int k = 0; k < 16; k++) {
            v = fmaf(0.5f, v, h[k]);
            const bool f = (v >= 1.0f);
            sp[k] = f ? 1.0f : 0.0f;
            v = f ? 0.0f : v;
        }
#pragma unroll
        for (int k = 0; k < 16; k++) __stcg(op + (size_t)k * BH, sp[k]);
        hp += (size_t)16 * BH;
        op += (size_t)16 * BH;
    }
}

// ---------------------------------------------------------------------------
extern "C" void kernel_launch(void* const* d_in, const int* in_sizes, int n_in,
                              void* d_out, int out_size) {
    const float* x = (const float*)d_in[0];   // (256,128,512)
    const float* W = (const float*)d_in[1];   // (512,512)
    const float* b = (const float*)d_in[2];   // (512,)
    float* out = (float*)d_out;               // (256,128,512)

    dim3 ggrid(N_TOT / BN, M_TOT / BM);       // (4, 256)
    gemm_bias_kernel<<<ggrid, 256>>>(x, W, b);

    lif_scan_kernel<<<BH / 256, 256>>>(out);
}